// round 9
// baseline (speedup 1.0000x reference)
#include <cuda_runtime.h>
#include <cuda_fp16.h>
#include <cstdint>

// Emu3 VQ vector quantizer — R9 (R8 + split argmin for ncu observability,
// launch_bounds reg cap, 2-group unroll).
// x: (1,2,4,64,64) fp32 -> N=8192 rows of C=4.  E: (32768,4) fp32.
// Outputs (float32): z_q_st (32768) | qloss (1) | codes (8192).

#define N_ROWS   8192
#define N_CODES  32768
#define ROWTILES 32       // 8192 rows / 256 threads
#define KSPLIT   32
#define KPER     1024     // 32*1024 = 32768
#define NGROUP   (KPER / 16)
#define CAP      12       // buffered candidate groups per thread (+1 dump slot)

__device__ unsigned long long g_best[N_ROWS];   // zero-init; holds ~minkey
__device__ float g_lp[32];
__device__ int   g_ctr;

__device__ __forceinline__ unsigned int h2u(__half2 h) {
    return *reinterpret_cast<unsigned int*>(&h);
}
__device__ __forceinline__ __half2 u2h(unsigned int u) {
    return *reinterpret_cast<__half2*>(&u);
}

// ---------- main argmin (y0 selects which half of the k-splits) ----------
__global__ void __launch_bounds__(256, 3) argmin_kernel(const float* __restrict__ x,
                                                        const float* __restrict__ E,
                                                        int y0) {
    __shared__ __align__(16) uint4  sEh[KPER / 2];   //  8 KB: 4 half2 per 2 codes
    __shared__ __align__(16) float4 sE32[KPER];      // 16 KB: fp32 E slice
    __shared__ float see[KPER];                      //  4 KB: ref-rounded ||e||^2
    __shared__ unsigned int sbuf[(CAP + 1) * 256];   // 13 KB (+dump row)

    const int tid = threadIdx.x;
    const int k0 = (y0 + blockIdx.y) * KPER;
    const float4* Ef = reinterpret_cast<const float4*>(E);

    // stage: fp32 slice + ||e||^2 + scaled fp16 pairs
    const float S = 32768.0f;
    for (int p = tid; p < KPER / 2; p += 256) {
        float4 a = Ef[k0 + 2 * p];
        float4 b = Ef[k0 + 2 * p + 1];
        sE32[2 * p]     = a;
        sE32[2 * p + 1] = b;
        see[2 * p] = __fadd_rn(__fadd_rn(__fadd_rn(__fmul_rn(a.x, a.x), __fmul_rn(a.y, a.y)),
                                         __fmul_rn(a.z, a.z)), __fmul_rn(a.w, a.w));
        see[2 * p + 1] = __fadd_rn(__fadd_rn(__fadd_rn(__fmul_rn(b.x, b.x), __fmul_rn(b.y, b.y)),
                                             __fmul_rn(b.z, b.z)), __fmul_rn(b.w, b.w));
        uint4 v;
        v.x = h2u(__floats2half2_rn(a.x * S, b.x * S));
        v.y = h2u(__floats2half2_rn(a.y * S, b.y * S));
        v.z = h2u(__floats2half2_rn(a.z * S, b.z * S));
        v.w = h2u(__floats2half2_rn(a.w * S, b.w * S));
        sEh[p] = v;
    }
    __syncthreads();

    // this thread's row
    const int n = blockIdx.x * 256 + tid;
    float q0, q1, q2, q3;
    {
        const float* xb = x + ((n >> 12) * 16384) + (n & 4095);
        q0 = xb[0]; q1 = xb[4096]; q2 = xb[8192]; q3 = xb[12288];
    }
    const float xx = __fadd_rn(__fadd_rn(__fadd_rn(__fmul_rn(q0, q0), __fmul_rn(q1, q1)),
                                         __fmul_rn(q2, q2)), __fmul_rn(q3, q3));
    const float sabs = fabsf(q0) + fabsf(q1) + fabsf(q2) + fabsf(q3);
    // margin in c' units: fp16 dot error + reference d-quantization + fp16 thr arithmetic
    const float marg = __fmaf_rn(xx, 8e-3f, __fmaf_rn(sabs, 4e-3f, 8e-3f));
    const __half2 marg2 = __half2half2(__float2half_ru(marg));

    const __half2 xh0 = __floats2half2_rn(q0, q0);
    const __half2 xh1 = __floats2half2_rn(q1, q1);
    const __half2 xh2 = __floats2half2_rn(q2, q2);
    const __half2 xh3 = __floats2half2_rn(q3, q3);

    __half2 thr2 = __half2half2(__ushort_as_half((unsigned short)0xFBFFu));  // -65504
    unsigned int cnt = 0;

#pragma unroll 2
    for (int g = 0; g < NGROUP; g++) {
        const uint4* gp = &sEh[g * 8];
        __half2 acc[8];
#pragma unroll
        for (int j = 0; j < 8; j++) {
            uint4 v = gp[j];
            __half2 a = __hmul2(xh0, u2h(v.x));
            a = __hfma2(xh1, u2h(v.y), a);
            a = __hfma2(xh2, u2h(v.z), a);
            a = __hfma2(xh3, u2h(v.w), a);
            acc[j] = a;
        }
        __half2 m01 = __hmax2(acc[0], acc[1]);
        __half2 m23 = __hmax2(acc[2], acc[3]);
        __half2 m45 = __hmax2(acc[4], acc[5]);
        __half2 m67 = __hmax2(acc[6], acc[7]);
        __half2 mx  = __hmax2(__hmax2(m01, m23), __hmax2(m45, m67));
        __half2 m2  = __hmax2(mx, __lowhigh2highlow(mx));   // both lanes = group max
        unsigned int msk = __hgt2_mask(m2, thr2);
        thr2 = __hmax2(thr2, __hsub2(m2, marg2));           // no-op when not triggered
        // branchless, clobber-free: non-triggers write the dump slot (CAP)
        unsigned int slot = (msk != 0u) ? min(cnt, (unsigned int)(CAP - 1))
                                        : (unsigned int)CAP;
        sbuf[slot * 256 + tid] = (unsigned int)g;
        cnt += (msk != 0u);
    }

    // exact reference-rounded evaluation of candidates from smem fp32
    unsigned long long key = ~0ull;
    if (cnt <= (unsigned int)CAP) {
        for (unsigned int i = 0; i < cnt; i++) {
            int kb = (int)sbuf[i * 256 + tid] * 16;
#pragma unroll
            for (int j = 0; j < 16; j++) {
                int kk = kb + j;
                float4 e = sE32[kk];
                float c = __fmul_rn(q0, e.x);
                c = __fmaf_rn(q1, e.y, c);
                c = __fmaf_rn(q2, e.z, c);
                c = __fmaf_rn(q3, e.w, c);
                float t = __fadd_rn(xx, see[kk]);
                float d = __fmaf_rn(c, -2.0f, t);   // == fl(t - 2c), 2c exact
                unsigned long long kv =
                    ((unsigned long long)__float_as_uint(d) << 32) | (unsigned int)(k0 + kk);
                key = min(key, kv);
            }
        }
    } else {
        // overflow fallback: exact scan of the whole slice (statistically rare)
        for (int kk = 0; kk < KPER; kk++) {
            float4 e = sE32[kk];
            float c = __fmul_rn(q0, e.x);
            c = __fmaf_rn(q1, e.y, c);
            c = __fmaf_rn(q2, e.z, c);
            c = __fmaf_rn(q3, e.w, c);
            float t = __fadd_rn(xx, see[kk]);
            float d = __fmaf_rn(c, -2.0f, t);
            unsigned long long kv =
                ((unsigned long long)__float_as_uint(d) << 32) | (unsigned int)(k0 + kk);
            key = min(key, kv);
        }
    }

    atomicMax(&g_best[n], ~key);
}

// ---------- finalize: gather z_q, straight-through, codes, loss; reset state ----------
__global__ void finalize_kernel(const float* __restrict__ x, const float* __restrict__ E,
                                float* __restrict__ out, int out_size) {
    __shared__ float red[256];
    __shared__ int isLast;
    int n = blockIdx.x * 256 + threadIdx.x;
    unsigned long long g = g_best[n];
    g_best[n] = 0ull;                                   // reset for next graph replay
    int k = (int)(unsigned int)((~g) & 0xFFFFFFFFull);  // ~g == minkey
    float4 e = reinterpret_cast<const float4*>(E)[k];
    float ev[4] = { e.x, e.y, e.z, e.w };
    int bt = n >> 12, hw = n & 4095;
    int xb = bt * 16384 + hw;
    float lsum = 0.0f;
#pragma unroll
    for (int c = 0; c < 4; c++) {
        int idx = xb + c * 4096;
        float xi = x[idx];
        float diff = __fadd_rn(ev[c], -xi);                  // fl(z_q - x)
        if (idx < out_size) out[idx] = __fadd_rn(xi, diff);  // x + sg(z_q - x)
        lsum = __fmaf_rn(diff, diff, lsum);
    }
    int ci = 32769 + n;
    if (ci < out_size) out[ci] = (float)k;

    red[threadIdx.x] = lsum;
    __syncthreads();
    for (int s = 128; s > 0; s >>= 1) {
        if (threadIdx.x < s) red[threadIdx.x] += red[threadIdx.x + s];
        __syncthreads();
    }
    if (threadIdx.x == 0) {
        g_lp[blockIdx.x] = red[0];
        __threadfence();
        int old = atomicAdd(&g_ctr, 1);
        isLast = (old == gridDim.x - 1) ? 1 : 0;
    }
    __syncthreads();
    if (isLast && threadIdx.x < 32) {
        float v = g_lp[threadIdx.x];
#pragma unroll
        for (int s = 16; s > 0; s >>= 1)
            v += __shfl_down_sync(0xFFFFFFFFu, v, s);
        if (threadIdx.x == 0) {
            g_ctr = 0;                                       // reset for next replay
            if (32768 < out_size) {
                float m = v * (1.0f / 32768.0f);             // exact /2^15
                out[32768] = __fadd_rn(m, __fmul_rn(0.1f, m));
            }
        }
    }
}

extern "C" void kernel_launch(void* const* d_in, const int* in_sizes, int n_in,
                              void* d_out, int out_size) {
    const float* x = (const float*)d_in[0];
    const float* E = (const float*)d_in[1];
    if (n_in >= 2 && in_sizes[0] > in_sizes[1]) {   // defensive: x is the smaller tensor
        x = (const float*)d_in[1];
        E = (const float*)d_in[0];
    }
    float* out = (float*)d_out;

    dim3 half_grid(ROWTILES, KSPLIT / 2);
    argmin_kernel<<<half_grid, 256>>>(x, E, 0);
    argmin_kernel<<<half_grid, 256>>>(x, E, KSPLIT / 2);
    finalize_kernel<<<32, 256>>>(x, E, out, out_size);
}

// round 11
// speedup vs baseline: 1.3770x; 1.3770x over previous
#include <cuda_runtime.h>
#include <cuda_fp16.h>
#include <cstdint>

// Emu3 VQ vector quantizer — R11 (R10 with smem under the 48KB static cap:
// byte-wide candidate buffer).
// x: (1,2,4,64,64) fp32 -> N=8192 rows of C=4.  E: (32768,4) fp32.
// Outputs (float32): z_q_st (32768) | qloss (1) | codes (8192).
//
// R9 profile: argmin is smem-crossbar bound (L1 55.8%) — every LDS.128 costs
// 4 cyc of 128B/cyc RF-writeback, and each thread redundantly loads E.
// R11: 2 rows per thread amortize each E load over two proxy dots, halving
// crossbar traffic to ~balance the HFMA2 pipe.

#define N_ROWS   8192
#define N_CODES  32768
#define ROWTILES 16       // 8192 rows / (256 threads * 2 rows)
#define KSPLIT   32
#define KPER     1024     // 32*1024 = 32768
#define NGROUP   (KPER / 16)
#define CAP      24       // buffered candidate groups per thread (+1 dump slot)

__device__ unsigned long long g_best[N_ROWS];   // zero-init; holds ~minkey
__device__ float g_lp[32];
__device__ int   g_ctr;

__device__ __forceinline__ unsigned int h2u(__half2 h) {
    return *reinterpret_cast<unsigned int*>(&h);
}
__device__ __forceinline__ __half2 u2h(unsigned int u) {
    return *reinterpret_cast<__half2*>(&u);
}

// ---------- main argmin ----------
__global__ void __launch_bounds__(256, 3) argmin_kernel(const float* __restrict__ x,
                                                        const float* __restrict__ E) {
    __shared__ __align__(16) uint4  sEh[KPER / 2];     //  8 KB: 4 half2 per 2 codes
    __shared__ __align__(16) float4 sE32[KPER];        // 16 KB: fp32 E slice
    __shared__ unsigned char sbuf[(CAP + 1) * 256];    // 6.25 KB (+dump row); enc < 128

    const int tid = threadIdx.x;
    const int k0 = blockIdx.y * KPER;
    const float4* Ef = reinterpret_cast<const float4*>(E);

    // stage: fp32 slice + scaled fp16 pairs
    const float S = 32768.0f;
    for (int p = tid; p < KPER / 2; p += 256) {
        float4 a = Ef[k0 + 2 * p];
        float4 b = Ef[k0 + 2 * p + 1];
        sE32[2 * p]     = a;
        sE32[2 * p + 1] = b;
        uint4 v;
        v.x = h2u(__floats2half2_rn(a.x * S, b.x * S));
        v.y = h2u(__floats2half2_rn(a.y * S, b.y * S));
        v.z = h2u(__floats2half2_rn(a.z * S, b.z * S));
        v.w = h2u(__floats2half2_rn(a.w * S, b.w * S));
        sEh[p] = v;
    }
    __syncthreads();

    // this thread's two rows (coalesced x loads: tid-consecutive -> hw-consecutive)
    const int na = blockIdx.x * 512 + tid;
    const int nb = na + 256;
    float qa0, qa1, qa2, qa3, qb0, qb1, qb2, qb3;
    {
        const float* pa = x + ((na >> 12) * 16384) + (na & 4095);
        const float* pb = x + ((nb >> 12) * 16384) + (nb & 4095);
        qa0 = pa[0]; qa1 = pa[4096]; qa2 = pa[8192]; qa3 = pa[12288];
        qb0 = pb[0]; qb1 = pb[4096]; qb2 = pb[8192]; qb3 = pb[12288];
    }
    const float xxa = __fadd_rn(__fadd_rn(__fadd_rn(__fmul_rn(qa0, qa0), __fmul_rn(qa1, qa1)),
                                          __fmul_rn(qa2, qa2)), __fmul_rn(qa3, qa3));
    const float xxb = __fadd_rn(__fadd_rn(__fadd_rn(__fmul_rn(qb0, qb0), __fmul_rn(qb1, qb1)),
                                          __fmul_rn(qb2, qb2)), __fmul_rn(qb3, qb3));
    const float sabsa = fabsf(qa0) + fabsf(qa1) + fabsf(qa2) + fabsf(qa3);
    const float sabsb = fabsf(qb0) + fabsf(qb1) + fabsf(qb2) + fabsf(qb3);
    // margin in c' units: fp16 dot error + reference d-quantization + fp16 thr arithmetic
    const __half2 marg2a = __half2half2(__float2half_ru(
        __fmaf_rn(xxa, 8e-3f, __fmaf_rn(sabsa, 4e-3f, 8e-3f))));
    const __half2 marg2b = __half2half2(__float2half_ru(
        __fmaf_rn(xxb, 8e-3f, __fmaf_rn(sabsb, 4e-3f, 8e-3f))));

    const __half2 xa0 = __floats2half2_rn(qa0, qa0);
    const __half2 xa1 = __floats2half2_rn(qa1, qa1);
    const __half2 xa2 = __floats2half2_rn(qa2, qa2);
    const __half2 xa3 = __floats2half2_rn(qa3, qa3);
    const __half2 xb0 = __floats2half2_rn(qb0, qb0);
    const __half2 xb1 = __floats2half2_rn(qb1, qb1);
    const __half2 xb2 = __floats2half2_rn(qb2, qb2);
    const __half2 xb3 = __floats2half2_rn(qb3, qb3);

    __half2 thra = __half2half2(__ushort_as_half((unsigned short)0xFBFFu));  // -65504
    __half2 thrb = thra;
    unsigned int cnt = 0;

    for (int g = 0; g < NGROUP; g++) {
        const uint4* gp = &sEh[g * 8];
        __half2 aca[8], acb[8];
#pragma unroll
        for (int j = 0; j < 8; j++) {
            uint4 v = gp[j];
            __half2 e0 = u2h(v.x), e1 = u2h(v.y), e2 = u2h(v.z), e3 = u2h(v.w);
            __half2 a = __hmul2(xa0, e0);
            a = __hfma2(xa1, e1, a);
            a = __hfma2(xa2, e2, a);
            a = __hfma2(xa3, e3, a);
            aca[j] = a;
            __half2 b = __hmul2(xb0, e0);
            b = __hfma2(xb1, e1, b);
            b = __hfma2(xb2, e2, b);
            b = __hfma2(xb3, e3, b);
            acb[j] = b;
        }
        __half2 ma = __hmax2(__hmax2(__hmax2(aca[0], aca[1]), __hmax2(aca[2], aca[3])),
                             __hmax2(__hmax2(aca[4], aca[5]), __hmax2(aca[6], aca[7])));
        __half2 mb = __hmax2(__hmax2(__hmax2(acb[0], acb[1]), __hmax2(acb[2], acb[3])),
                             __hmax2(__hmax2(acb[4], acb[5]), __hmax2(acb[6], acb[7])));
        ma = __hmax2(ma, __lowhigh2highlow(ma));   // both lanes = group max (row a)
        mb = __hmax2(mb, __lowhigh2highlow(mb));   // both lanes = group max (row b)
        unsigned int mka = __hgt2_mask(ma, thra);
        unsigned int mkb = __hgt2_mask(mb, thrb);
        thra = __hmax2(thra, __hsub2(ma, marg2a));  // no-op when not triggered
        thrb = __hmax2(thrb, __hsub2(mb, marg2b));
        // branchless, clobber-free: non-triggers write the dump slot (CAP)
        unsigned int sa = (mka != 0u) ? min(cnt, (unsigned int)(CAP - 1))
                                      : (unsigned int)CAP;
        sbuf[sa * 256 + tid] = (unsigned char)(g << 1);
        cnt += (mka != 0u);
        unsigned int sb = (mkb != 0u) ? min(cnt, (unsigned int)(CAP - 1))
                                      : (unsigned int)CAP;
        sbuf[sb * 256 + tid] = (unsigned char)((g << 1) | 1);
        cnt += (mkb != 0u);
    }

    // exact reference-rounded evaluation of candidates from smem fp32
    unsigned long long keya = ~0ull, keyb = ~0ull;
    if (cnt <= (unsigned int)CAP) {
        for (unsigned int i = 0; i < cnt; i++) {
            unsigned int enc = (unsigned int)sbuf[i * 256 + tid];
            int r  = (int)(enc & 1u);
            int kb = (int)(enc >> 1) * 16;
            float q0 = r ? qb0 : qa0, q1 = r ? qb1 : qa1;
            float q2 = r ? qb2 : qa2, q3 = r ? qb3 : qa3;
            float txx = r ? xxb : xxa;
            unsigned long long emin = ~0ull;
#pragma unroll
            for (int j = 0; j < 16; j++) {
                int kk = kb + j;
                float4 e = sE32[kk];
                float ee = __fadd_rn(__fadd_rn(__fadd_rn(__fmul_rn(e.x, e.x), __fmul_rn(e.y, e.y)),
                                               __fmul_rn(e.z, e.z)), __fmul_rn(e.w, e.w));
                float c = __fmul_rn(q0, e.x);
                c = __fmaf_rn(q1, e.y, c);
                c = __fmaf_rn(q2, e.z, c);
                c = __fmaf_rn(q3, e.w, c);
                float t = __fadd_rn(txx, ee);
                float d = __fmaf_rn(c, -2.0f, t);   // == fl(t - 2c), 2c exact
                unsigned long long kv =
                    ((unsigned long long)__float_as_uint(d) << 32) | (unsigned int)(k0 + kk);
                emin = min(emin, kv);
            }
            if (r) keyb = min(keyb, emin); else keya = min(keya, emin);
        }
    } else {
        // overflow fallback: exact scan of the whole slice for both rows (rare)
        for (int kk = 0; kk < KPER; kk++) {
            float4 e = sE32[kk];
            float ee = __fadd_rn(__fadd_rn(__fadd_rn(__fmul_rn(e.x, e.x), __fmul_rn(e.y, e.y)),
                                           __fmul_rn(e.z, e.z)), __fmul_rn(e.w, e.w));
            float ca = __fmul_rn(qa0, e.x);
            ca = __fmaf_rn(qa1, e.y, ca);
            ca = __fmaf_rn(qa2, e.z, ca);
            ca = __fmaf_rn(qa3, e.w, ca);
            float da = __fmaf_rn(ca, -2.0f, __fadd_rn(xxa, ee));
            keya = min(keya, ((unsigned long long)__float_as_uint(da) << 32)
                              | (unsigned int)(k0 + kk));
            float cb = __fmul_rn(qb0, e.x);
            cb = __fmaf_rn(qb1, e.y, cb);
            cb = __fmaf_rn(qb2, e.z, cb);
            cb = __fmaf_rn(qb3, e.w, cb);
            float db = __fmaf_rn(cb, -2.0f, __fadd_rn(xxb, ee));
            keyb = min(keyb, ((unsigned long long)__float_as_uint(db) << 32)
                              | (unsigned int)(k0 + kk));
        }
    }

    atomicMax(&g_best[na], ~keya);
    atomicMax(&g_best[nb], ~keyb);
}

// ---------- finalize: gather z_q, straight-through, codes, loss; reset state ----------
__global__ void finalize_kernel(const float* __restrict__ x, const float* __restrict__ E,
                                float* __restrict__ out, int out_size) {
    __shared__ float red[256];
    __shared__ int isLast;
    int n = blockIdx.x * 256 + threadIdx.x;
    unsigned long long g = g_best[n];
    g_best[n] = 0ull;                                   // reset for next graph replay
    int k = (int)(unsigned int)((~g) & 0xFFFFFFFFull);  // ~g == minkey
    float4 e = reinterpret_cast<const float4*>(E)[k];
    float ev[4] = { e.x, e.y, e.z, e.w };
    int bt = n >> 12, hw = n & 4095;
    int xb = bt * 16384 + hw;
    float lsum = 0.0f;
#pragma unroll
    for (int c = 0; c < 4; c++) {
        int idx = xb + c * 4096;
        float xi = x[idx];
        float diff = __fadd_rn(ev[c], -xi);                  // fl(z_q - x)
        if (idx < out_size) out[idx] = __fadd_rn(xi, diff);  // x + sg(z_q - x)
        lsum = __fmaf_rn(diff, diff, lsum);
    }
    int ci = 32769 + n;
    if (ci < out_size) out[ci] = (float)k;

    red[threadIdx.x] = lsum;
    __syncthreads();
    for (int s = 128; s > 0; s >>= 1) {
        if (threadIdx.x < s) red[threadIdx.x] += red[threadIdx.x + s];
        __syncthreads();
    }
    if (threadIdx.x == 0) {
        g_lp[blockIdx.x] = red[0];
        __threadfence();
        int old = atomicAdd(&g_ctr, 1);
        isLast = (old == gridDim.x - 1) ? 1 : 0;
    }
    __syncthreads();
    if (isLast && threadIdx.x < 32) {
        float v = g_lp[threadIdx.x];
#pragma unroll
        for (int s = 16; s > 0; s >>= 1)
            v += __shfl_down_sync(0xFFFFFFFFu, v, s);
        if (threadIdx.x == 0) {
            g_ctr = 0;                                       // reset for next replay
            if (32768 < out_size) {
                float m = v * (1.0f / 32768.0f);             // exact /2^15
                out[32768] = __fadd_rn(m, __fmul_rn(0.1f, m));
            }
        }
    }
}

extern "C" void kernel_launch(void* const* d_in, const int* in_sizes, int n_in,
                              void* d_out, int out_size) {
    const float* x = (const float*)d_in[0];
    const float* E = (const float*)d_in[1];
    if (n_in >= 2 && in_sizes[0] > in_sizes[1]) {   // defensive: x is the smaller tensor
        x = (const float*)d_in[1];
        E = (const float*)d_in[0];
    }
    float* out = (float*)d_out;

    dim3 grid(ROWTILES, KSPLIT);
    argmin_kernel<<<grid, 256>>>(x, E);
    finalize_kernel<<<32, 256>>>(x, E, out, out_size);
}